// round 14
// baseline (speedup 1.0000x reference)
#include <cuda_runtime.h>
#include <cuda_bf16.h>
#include <cstdint>

// Problem shape (fixed by setup_inputs): preds [T,B,C] f32, targets [B,L] i64.
#define TT 128
#define BB 128
#define CC 8192
#define LL 50
#define NSLOT 51         // slot 0 = blank, slots 1..50 = labels
#define NSTREAM (TT*BB)  // 16384 streaming blocks
#define NPAIR (BB*NSLOT) // 6528

// Scratch (zero at module load; the finisher restores zeros every call; the
// launch boundary orders those stores before the next graph replay).
__device__ float    g_acc[NPAIR];        // per-(b,slot) sum_t exp(x)/Z
__device__ unsigned g_done;              // global completion counter

// Fast exp on the FMA pipe (no MUFU). Rel err ~5e-5.
__device__ __forceinline__ float fast_exp(float x) {
    const float L2E = 1.4426950408889634f;
    float t  = fmaf(x, L2E, 12582912.0f);
    float nf = t - 12582912.0f;
    float f  = fmaf(x, L2E, -nf);
    int   ni = __float_as_int(t) - 0x4B400000;
    float sc = __int_as_float((ni << 23) + 0x3F800000);
    float p = fmaf(f, 0.009618129f, 0.05550411f);
    p = fmaf(f, p, 0.2402265f);
    p = fmaf(f, p, 0.6931472f);
    float fp = f * p;
    return fmaf(fp, sc, sc);
}

// Fast natural log on the FMA pipe (no MUFU). Abs err ~1e-5.
__device__ __forceinline__ float fast_logf(float a) {
    int   e = (__float_as_int(a) - 0x3f2aaaab) & 0xff800000;
    float m = __int_as_float(__float_as_int(a) - e);   // m in [2/3, 4/3)
    float i = (float)e * 1.19209290e-7f;               // e / 2^23
    float f = m - 1.0f;
    float s = f * f;
    float r = fmaf(0.230836749f, f, -0.279208571f);
    float t = fmaf(0.331826031f, f, -0.498910338f);
    r = fmaf(r, s, t);
    r = fmaf(r, s, f);
    return fmaf(i, 0.693147182f, r);
}

__device__ __forceinline__ void red_release_add(unsigned* p, unsigned v) {
    asm volatile("red.release.gpu.global.add.u32 [%0], %1;"
                 :: "l"(p), "r"(v) : "memory");
}
__device__ __forceinline__ unsigned ld_relaxed(const unsigned* p) {
    unsigned r;
    asm volatile("ld.relaxed.gpu.global.u32 %0, [%1];" : "=r"(r) : "l"(p) : "memory");
    return r;
}
__device__ __forceinline__ unsigned ld_acquire(const unsigned* p) {
    unsigned r;
    asm volatile("ld.acquire.gpu.global.u32 %0, [%1];" : "=r"(r) : "l"(p) : "memory");
    return r;
}

// ---------------------------------------------------------------------------
// Blocks [0, NSTREAM): exact R10 stream + one fire-and-forget red.release.
// Block NSTREAM (scheduled last, during the drain): spins, acquires, does
// the epilogue with scalar temps only (NO register arrays -- the 32-reg cap
// from __launch_bounds__(256,8) is what keeps the stream at 8 blocks/SM).
// ---------------------------------------------------------------------------
__global__ __launch_bounds__(256, 8) void ace_kernel(
    const float* __restrict__ preds,
    const long long* __restrict__ tgt,
    float* __restrict__ out)
{
    int blk = blockIdx.x;
    int tid = threadIdx.x;

    if (blk < NSTREAM) {
        // ================= streaming path (R10, 74.3 us) ==================
        int b = blk & (BB - 1);
        const float* rowf = preds + (size_t)blk * CC;

        int c = 0;                        // slot 0 -> blank class 0
        if (tid >= 1 && tid < NSLOT) {
            long long l = tgt[(size_t)b * LL + (tid - 1)];
            if (l > 0 && l < CC) c = (int)l;
        }
        float xc = 0.0f;
        if (tid < NSLOT) xc = __ldg(rowf + c);   // in flight during stream

        const float4* row = reinterpret_cast<const float4*>(rowf);
        float acc = 0.0f;
#pragma unroll
        for (int i = 0; i < 8; i++) {
            float4 v = row[tid + i * 256];       // 8 front-batched LDG.128
            acc += fast_exp(v.x) + fast_exp(v.y) + fast_exp(v.z) + fast_exp(v.w);
        }
#pragma unroll
        for (int o = 16; o > 0; o >>= 1)
            acc += __shfl_xor_sync(0xFFFFFFFFu, acc, o);

        __shared__ float s[8];
        if ((tid & 31) == 0) s[tid >> 5] = acc;
        __syncthreads();

        if (tid < NSLOT) {
            float z = s[0] + s[1] + s[2] + s[3] + s[4] + s[5] + s[6] + s[7];
            atomicAdd(&g_acc[b * NSLOT + tid], fast_exp(xc) * (1.0f / z));
        }

        __syncthreads();                  // block's REDGs precede the release
        if (tid == 0) red_release_add(&g_done, 1u);
        return;
    }

    // ===================== single finisher block ==========================
    __shared__ float snpos[BB];
    __shared__ float sred[8];

    // Phase A (pre-spin): per-b valid-positive-label counts. tid<128 -> b.
    if (tid < BB) {
        const long long* tb = tgt + (size_t)tid * LL;
        float npos = 0.0f;
#pragma unroll 5
        for (int j = 0; j < LL; j++) {
            long long l = tb[j];
            npos += (l > 0 && l < CC) ? 1.0f : 0.0f;
        }
        snpos[tid] = npos;
    }
    __syncthreads();

    // Wait for all streamers.
    if (tid == 0) {
        while (ld_relaxed(&g_done) != NSTREAM) __nanosleep(64);
        (void)ld_acquire(&g_done);        // sync with the release sequence
        g_done = 0u;                      // restore invariant for next replay
    }
    __syncthreads();

    // Phase B: 6528 (b,slot) pairs, 2 per thread per iteration (scalar temps
    // only). All g_acc loads are L2-hot (just written by REDGs); tgt is
    // L1-hot from phase A.
    const float LOG_T = 4.852030263919617f;         // ln(128)
    float lsum = 0.0f;
#pragma unroll
    for (int m = 0; m < 13; m++) {
        int i0 = tid + m * 512;
        int i1 = i0 + 256;
        float t0 = (i0 < NPAIR) ? g_acc[i0] : 1.0f;
        float t1 = (i1 < NPAIR) ? g_acc[i1] : 1.0f;
        if (i0 < NPAIR) {
            g_acc[i0] = 0.0f;             // restore invariant
            int b = i0 / NSLOT, slot = i0 - b * NSLOT;
            float w = (slot == 0) ? ((float)TT - snpos[b])
                : (((tgt[b * LL + slot - 1] > 0) && (tgt[b * LL + slot - 1] < CC)) ? 1.0f : 0.0f);
            if (w != 0.0f) lsum += w * (fast_logf(t0) - LOG_T);
        }
        if (i1 < NPAIR) {
            g_acc[i1] = 0.0f;
            int b = i1 / NSLOT, slot = i1 - b * NSLOT;
            float w = (slot == 0) ? ((float)TT - snpos[b])
                : (((tgt[b * LL + slot - 1] > 0) && (tgt[b * LL + slot - 1] < CC)) ? 1.0f : 0.0f);
            if (w != 0.0f) lsum += w * (fast_logf(t1) - LOG_T);
        }
    }

    // Block reduce 256 -> 1, single plain store.
#pragma unroll
    for (int o = 16; o > 0; o >>= 1)
        lsum += __shfl_xor_sync(0xFFFFFFFFu, lsum, o);
    if ((tid & 31) == 0) sred[tid >> 5] = lsum;
    __syncthreads();
    if (tid == 0) {
        float v = sred[0] + sred[1] + sred[2] + sred[3]
                + sred[4] + sred[5] + sred[6] + sred[7];
        *out = -v * (1.0f / ((float)BB * (float)TT));
    }
}

extern "C" void kernel_launch(void* const* d_in, const int* in_sizes, int n_in,
                              void* d_out, int out_size)
{
    const float*     preds = (const float*)d_in[0];
    const long long* tgt   = (const long long*)d_in[1];
    float*           out   = (float*)d_out;

    ace_kernel<<<NSTREAM + 1, 256>>>(preds, tgt, out);
}

// round 15
// speedup vs baseline: 1.0965x; 1.0965x over previous
#include <cuda_runtime.h>
#include <cuda_bf16.h>
#include <cstdint>

// Problem shape (fixed by setup_inputs): preds [T,B,C] f32, targets [B,L] i64.
#define TT 128
#define BB 128
#define CC 8192
#define LL 50
#define NSLOT 51         // slot 0 = blank, slots 1..50 = labels
#define NPAIR (BB*NSLOT) // 6528

// Dense accumulator: g_acc[b][slot] = sum_t exp(x[t,b,c_slot])/Z[t,b].
// Zero at module load; finish_kernel re-zeroes after reading -> invariant
// holds across graph replays.
__device__ float g_acc[NPAIR];

// Fast exp on the FMA pipe (no MUFU). Rel err ~5e-5.
__device__ __forceinline__ float fast_exp(float x) {
    const float L2E = 1.4426950408889634f;
    float t  = fmaf(x, L2E, 12582912.0f);
    float nf = t - 12582912.0f;
    float f  = fmaf(x, L2E, -nf);
    int   ni = __float_as_int(t) - 0x4B400000;
    float sc = __int_as_float((ni << 23) + 0x3F800000);
    float p = fmaf(f, 0.009618129f, 0.05550411f);
    p = fmaf(f, p, 0.2402265f);
    p = fmaf(f, p, 0.6931472f);
    float fp = f * p;
    return fmaf(fp, sc, sc);
}

// Fast natural log on the FMA pipe (no MUFU). Abs err ~1e-5.
__device__ __forceinline__ float fast_logf(float a) {
    int   e = (__float_as_int(a) - 0x3f2aaaab) & 0xff800000;
    float m = __int_as_float(__float_as_int(a) - e);   // m in [2/3, 4/3)
    float i = (float)e * 1.19209290e-7f;               // e / 2^23
    float f = m - 1.0f;
    float s = f * f;
    float r = fmaf(0.230836749f, f, -0.279208571f);
    float t = fmaf(0.331826031f, f, -0.498910338f);
    r = fmaf(r, s, t);
    r = fmaf(r, s, f);
    return fmaf(i, 0.693147182f, r);
}

// ---------------------------------------------------------------------------
// Kernel 1: one block per (t,b) row (exact R10 best stream: ~74.3 us).
//   label -> fire sparse gather early -> stream 32 KB -> Z -> REDG.
// ---------------------------------------------------------------------------
__global__ __launch_bounds__(256) void zsum_kernel(
    const float* __restrict__ preds,
    const long long* __restrict__ tgt)
{
    int tb  = blockIdx.x;                 // = t*BB + b
    int b   = tb & (BB - 1);
    int tid = threadIdx.x;

    const float* rowf = preds + (size_t)tb * CC;

    int c = 0;                            // slot 0 -> blank class 0
    if (tid >= 1 && tid < NSLOT) {
        long long l = tgt[(size_t)b * LL + (tid - 1)];
        if (l > 0 && l < CC) c = (int)l;  // invalid -> class 0 (weight 0 later)
    }
    float xc = 0.0f;
    if (tid < NSLOT) xc = __ldg(rowf + c);   // in flight during the stream

    const float4* row = reinterpret_cast<const float4*>(rowf);
    float acc = 0.0f;
#pragma unroll
    for (int i = 0; i < 8; i++) {
        float4 v = row[tid + i * 256];    // 8 front-batched LDG.128
        acc += fast_exp(v.x) + fast_exp(v.y) + fast_exp(v.z) + fast_exp(v.w);
    }
#pragma unroll
    for (int o = 16; o > 0; o >>= 1)
        acc += __shfl_xor_sync(0xFFFFFFFFu, acc, o);

    __shared__ float s[8];
    if ((tid & 31) == 0) s[tid >> 5] = acc;
    __syncthreads();

    if (tid < NSLOT) {
        float z = s[0] + s[1] + s[2] + s[3] + s[4] + s[5] + s[6] + s[7];
        atomicAdd(&g_acc[b * NSLOT + tid], fast_exp(xc) * (1.0f / z));
    }
}

// ---------------------------------------------------------------------------
// Kernel 2: ONE block, 1024 threads (no 128-block ramp). All memory fetched
// in two overlapped MLP-7 rounds (L2 is thrashed after the 512 MB stream, so
// everything is DRAM-cold -- batch it, don't chain it). No atomics anywhere:
// shfl-group reductions + plain stores. Single STG writes *out.
// ---------------------------------------------------------------------------
__global__ __launch_bounds__(1024) void finish_kernel(
    const long long* __restrict__ tgt,
    float* __restrict__ out)
{
    int tid = threadIdx.x;
    __shared__ float snpos[BB];
    __shared__ float sred[32];

    // Round 1 (issued first, fills the MLP window): all 6528 g_acc values.
    float tv[7];
#pragma unroll
    for (int m = 0; m < 7; m++) {
        int idx = tid + m * 1024;
        tv[m] = (idx < NPAIR) ? g_acc[idx] : 1.0f;
    }

    // Round 2 (overlaps round 1): labels. 8 threads per b; thread k of the
    // group loads labels k, k+8, ..., then 3-step shfl reduces within the
    // 8-lane group. Plain smem store -- no atomics.
    {
        int b8 = tid >> 3, k = tid & 7;
        const long long* tb = tgt + (size_t)b8 * LL;
        float npos = 0.0f;
#pragma unroll
        for (int j = 0; j < 7; j++) {
            int li = k + j * 8;
            if (li < LL) {
                long long l = tb[li];
                npos += (l > 0 && l < CC) ? 1.0f : 0.0f;
            }
        }
        npos += __shfl_xor_sync(0xFFFFFFFFu, npos, 1);
        npos += __shfl_xor_sync(0xFFFFFFFFu, npos, 2);
        npos += __shfl_xor_sync(0xFFFFFFFFu, npos, 4);
        if (k == 0) snpos[b8] = npos;
    }

    // Zero g_acc behind ourselves (fire-and-forget stores).
#pragma unroll
    for (int m = 0; m < 7; m++) {
        int idx = tid + m * 1024;
        if (idx < NPAIR) g_acc[idx] = 0.0f;
    }
    __syncthreads();

    // Weights + FMA-pipe logs. tgt re-reads are L1-hot (loaded above).
    const float LOG_T = 4.852030263919617f;         // ln(128)
    float lsum = 0.0f;
#pragma unroll
    for (int m = 0; m < 7; m++) {
        int idx = tid + m * 1024;
        if (idx < NPAIR) {
            int b = idx / NSLOT, slot = idx - b * NSLOT;
            float w;
            if (slot == 0) {
                w = (float)TT - snpos[b];
            } else {
                long long l = tgt[(size_t)b * LL + slot - 1];
                w = (l > 0 && l < CC) ? 1.0f : 0.0f;
            }
            if (w != 0.0f) lsum += w * (fast_logf(tv[m]) - LOG_T);
        }
    }

    // Block reduce 1024 -> 1; single plain store (no atomic, no pre-zero).
#pragma unroll
    for (int o = 16; o > 0; o >>= 1)
        lsum += __shfl_xor_sync(0xFFFFFFFFu, lsum, o);
    if ((tid & 31) == 0) sred[tid >> 5] = lsum;
    __syncthreads();
    if (tid < 32) {
        float v = sred[tid];
#pragma unroll
        for (int o = 16; o > 0; o >>= 1)
            v += __shfl_xor_sync(0xFFFFFFFFu, v, o);
        if (tid == 0)
            *out = -v * (1.0f / ((float)BB * (float)TT));
    }
}

extern "C" void kernel_launch(void* const* d_in, const int* in_sizes, int n_in,
                              void* d_out, int out_size)
{
    const float*     preds = (const float*)d_in[0];
    const long long* tgt   = (const long long*)d_in[1];
    float*           out   = (float*)d_out;

    zsum_kernel<<<TT * BB, 256>>>(preds, tgt);
    finish_kernel<<<1, 1024>>>(tgt, out);
}

// round 17
// speedup vs baseline: 1.1277x; 1.0284x over previous
#include <cuda_runtime.h>
#include <cuda_bf16.h>
#include <cstdint>

// Problem shape (fixed by setup_inputs): preds [T,B,C] f32, targets [B,L] i64.
#define TT 128
#define BB 128
#define CC 8192
#define LL 50
#define NSLOT 51   // slot 0 = blank, slots 1..50 = labels

// Dense accumulator: g_acc[b][slot] = sum_t exp(x[t,b,c_slot])/Z[t,b].
// Zero at module load; finish_kernel re-zeroes after reading -> invariant
// holds across graph replays. 26 KB, L2-resident (stream uses evict-first).
__device__ float g_acc[BB * NSLOT];

// Fast exp on the FMA pipe (no MUFU). Rel err ~5e-5.
__device__ __forceinline__ float fast_exp(float x) {
    const float L2E = 1.4426950408889634f;
    float t  = fmaf(x, L2E, 12582912.0f);
    float nf = t - 12582912.0f;
    float f  = fmaf(x, L2E, -nf);
    int   ni = __float_as_int(t) - 0x4B400000;
    float sc = __int_as_float((ni << 23) + 0x3F800000);
    float p = fmaf(f, 0.009618129f, 0.05550411f);
    p = fmaf(f, p, 0.2402265f);
    p = fmaf(f, p, 0.6931472f);
    float fp = f * p;
    return fmaf(fp, sc, sc);
}

// Fast natural log on the FMA pipe (no MUFU). Abs err ~1e-5.
__device__ __forceinline__ float fast_logf(float a) {
    int   e = (__float_as_int(a) - 0x3f2aaaab) & 0xff800000;
    float m = __int_as_float(__float_as_int(a) - e);   // m in [2/3, 4/3)
    float i = (float)e * 1.19209290e-7f;               // e / 2^23
    float f = m - 1.0f;
    float s = f * f;
    float r = fmaf(0.230836749f, f, -0.279208571f);
    float t = fmaf(0.331826031f, f, -0.498910338f);
    r = fmaf(r, s, t);
    r = fmaf(r, s, f);
    return fmaf(i, 0.693147182f, r);
}

// Evict-first streaming load (keeps the 512 MB stream out of L2's working
// set, so g_acc/tgt stay L2-resident for the REDGs and the finisher).
__device__ __forceinline__ float4 ldcs_f4(const float4* p) {
    float4 v;
    asm volatile("ld.global.cs.v4.f32 {%0,%1,%2,%3}, [%4];"
                 : "=f"(v.x), "=f"(v.y), "=f"(v.z), "=f"(v.w) : "l"(p));
    return v;
}

// ---------------------------------------------------------------------------
// Kernel 1: one block per (t,b) row (R10 structure, best-measured stream).
//   label -> fire sparse gather early -> stream 32 KB (evict-first) -> Z
//   -> relaxed REDG into dense g_acc.
// ---------------------------------------------------------------------------
__global__ __launch_bounds__(256) void zsum_kernel(
    const float* __restrict__ preds,
    const long long* __restrict__ tgt,
    float* __restrict__ out)
{
    int tb  = blockIdx.x;                 // = t*BB + b
    int b   = tb & (BB - 1);
    int tid = threadIdx.x;
    if (tb == 0 && tid == 0) *out = 0.0f;

    const float* rowf = preds + (size_t)tb * CC;

    int c = 0;                            // slot 0 -> blank class 0
    if (tid >= 1 && tid < NSLOT) {
        long long l = tgt[(size_t)b * LL + (tid - 1)];
        if (l > 0 && l < CC) c = (int)l;  // invalid -> class 0 (weight 0 later)
    }
    float xc = 0.0f;
    if (tid < NSLOT) xc = __ldg(rowf + c);   // in flight during the stream

    const float4* row = reinterpret_cast<const float4*>(rowf);
    float acc = 0.0f;
#pragma unroll
    for (int i = 0; i < 8; i++) {
        float4 v = ldcs_f4(row + tid + i * 256);  // 8 front-batched LDG.128.CS
        acc += fast_exp(v.x) + fast_exp(v.y) + fast_exp(v.z) + fast_exp(v.w);
    }
#pragma unroll
    for (int o = 16; o > 0; o >>= 1)
        acc += __shfl_xor_sync(0xFFFFFFFFu, acc, o);

    __shared__ float s[8];
    if ((tid & 31) == 0) s[tid >> 5] = acc;
    __syncthreads();

    if (tid < NSLOT) {
        float z = s[0] + s[1] + s[2] + s[3] + s[4] + s[5] + s[6] + s[7];
        atomicAdd(&g_acc[b * NSLOT + tid], fast_exp(xc) * (1.0f / z));
    }
}

// ---------------------------------------------------------------------------
// Kernel 2: 64 blocks x 128 threads; each block owns TWO b-rows (one slot
// per thread) and issues ONE atomicAdd -- halves the same-address convoy
// and the block-ramp count vs the 128-block shape.
//   Thread layout: bh = tid>>6 (which of the 2 rows), j = tid&63 (slot).
// ---------------------------------------------------------------------------
__global__ __launch_bounds__(128) void finish_kernel(
    const long long* __restrict__ tgt,
    float* __restrict__ out)
{
    int tid = threadIdx.x;
    int bh  = tid >> 6;                   // 0 or 1
    int j   = tid & 63;                   // slot index (0..63; <51 active)
    int b   = blockIdx.x * 2 + bh;

    float total = 0.0f;
    float wpos  = 0.0f;
    if (j < NSLOT) {
        total = g_acc[b * NSLOT + j];
        g_acc[b * NSLOT + j] = 0.0f;      // restore invariant for next replay
        if (j >= 1) {
            long long l = tgt[(size_t)b * LL + (j - 1)];
            wpos = (l > 0 && l < CC) ? 1.0f : 0.0f;
        }
    }

    // npos per b-row: reduce wpos over the 64-thread half (2 warps).
    __shared__ float sw[4];               // [bh*2 + warp-in-half]
    float f = wpos;
#pragma unroll
    for (int o = 16; o > 0; o >>= 1)
        f += __shfl_xor_sync(0xFFFFFFFFu, f, o);
    if ((tid & 31) == 0) sw[tid >> 5] = f;
    __syncthreads();
    float npos = sw[bh * 2] + sw[bh * 2 + 1];
    __syncthreads();

    const float LOG_T = 4.852030263919617f;    // ln(128)
    float contrib = 0.0f;
    if (j < NSLOT) {
        float w = (j == 0) ? ((float)TT - npos) : wpos;
        if (w != 0.0f) contrib = w * (fast_logf(total) - LOG_T);
    }
#pragma unroll
    for (int o = 16; o > 0; o >>= 1)
        contrib += __shfl_xor_sync(0xFFFFFFFFu, contrib, o);
    if ((tid & 31) == 0) sw[tid >> 5] = contrib;
    __syncthreads();
    if (tid == 0)
        atomicAdd(out, -(sw[0] + sw[1] + sw[2] + sw[3])
                           * (1.0f / ((float)BB * (float)TT)));
}

extern "C" void kernel_launch(void* const* d_in, const int* in_sizes, int n_in,
                              void* d_out, int out_size)
{
    const float*     preds = (const float*)d_in[0];
    const long long* tgt   = (const long long*)d_in[1];
    float*           out   = (float*)d_out;

    zsum_kernel<<<TT * BB, 256>>>(preds, tgt, out);
    finish_kernel<<<BB / 2, 128>>>(tgt, out);
}